// round 3
// baseline (speedup 1.0000x reference)
#include <cuda_runtime.h>
#include <math.h>

#define BATCH 2
#define NT    2048
#define NSEG1 1536
#define NSEG2 512
#define DM    1024
#define NH    16
#define HD    64

typedef unsigned long long u64;

// Scratch (static device arrays — no allocation)
static __device__ float g_qkv[BATCH * NT * 3 * DM];   // (b, n, 3*1024)
static __device__ float g_q[BATCH * NH * NT * HD];    // (b, h, n, d)
static __device__ float g_k[BATCH * NH * NT * HD];
static __device__ float g_v[BATCH * NH * NT * HD];
static __device__ float g_x[BATCH * NT * DM];         // attention out, (b, n, h*d)

// ---------------------------------------------------------------------------
// Packed fp32 helpers (Blackwell fma.rn.f32x2 — ptxas never auto-fuses)
// ---------------------------------------------------------------------------
__device__ __forceinline__ u64 ffma2(u64 a, u64 b, u64 c) {
    u64 d;
    asm("fma.rn.f32x2 %0, %1, %2, %3;" : "=l"(d) : "l"(a), "l"(b), "l"(c));
    return d;
}
__device__ __forceinline__ u64 fmul2(u64 a, u64 b) {
    u64 d;
    asm("mul.rn.f32x2 %0, %1, %2;" : "=l"(d) : "l"(a), "l"(b));
    return d;
}
__device__ __forceinline__ u64 pack2(float a, float b) {
    u64 r;
    asm("mov.b64 %0, {%1, %2};" : "=l"(r) : "f"(a), "f"(b));
    return r;
}
__device__ __forceinline__ float2 unpack2(u64 v) {
    float2 f;
    asm("mov.b64 {%0, %1}, %2;" : "=f"(f.x), "=f"(f.y) : "l"(v));
    return f;
}

// ---------------------------------------------------------------------------
// Fast exp on the FMA pipe (avoids MUFU rt=8 bottleneck); valid x <= 0
// ---------------------------------------------------------------------------
__device__ __forceinline__ float fexp(float x) {
    x = fmaxf(x, -80.0f);
    float t = x * 1.4426950408889634f;
    float n = rintf(t);
    float f = t - n;
    float z = f * 0.6931471805599453f;
    float p = 1.0f + z * (1.0f + z * (0.5f + z * (0.16666667f + z * (0.041666667f + z * 0.008333334f))));
    int ni = (int)n;
    float s = __int_as_float((ni + 127) << 23);
    return p * s;
}

// ---------------------------------------------------------------------------
// NT GEMM: C[m, n] = sum_k A[m, k] * B[n, k] + bias[n]
// 128x128x16 tiles, 256 threads, micro = 16 rows (8 packed pairs) x 4 cols.
// B is stored DUPLICATED in smem ((v,v) pairs) so FFMA2 has zero movs.
// Double-buffered: one __syncthreads per k-chunk.
// ---------------------------------------------------------------------------
__global__ void __launch_bounds__(256, 2)
gemm_nt(const float* __restrict__ A, const float* __restrict__ B,
        const float* __restrict__ bias, float* __restrict__ C,
        int N, int K,
        int aRPB, long long aBS,      // A rows-per-batch, batch stride (elems)
        int cRPB, long long cBS)      // C rows-per-batch, batch stride (elems)
{
    __shared__ float As[2][16][128];   // [k][m]
    __shared__ float Bd[2][16][256];   // [k][2n dup]

    const int tid = threadIdx.x;
    const int tx = tid & 31;          // cols 4*tx .. 4*tx+3
    const int ty = tid >> 5;          // rows 16*ty .. 16*ty+15
    const int m0 = blockIdx.y * 128;
    const int n0 = blockIdx.x * 128;

    const int lr = tid >> 1;          // loader row 0..127
    const int lg = tid & 1;           // k-half (8 floats)

    const int am = m0 + lr;
    const int ab = am / aRPB;
    const float* Arow = A + (long long)ab * aBS + (long long)(am - ab * aRPB) * K + 8 * lg;
    const float* Brow = B + (long long)(n0 + lr) * K + 8 * lg;

    u64 acc[8][4];
#pragma unroll
    for (int p = 0; p < 8; p++)
#pragma unroll
        for (int j = 0; j < 4; j++) acc[p][j] = 0ull;

    // preload chunk 0
    float4 a0 = *(const float4*)(Arow);
    float4 a1 = *(const float4*)(Arow + 4);
    float4 b0 = *(const float4*)(Brow);
    float4 b1 = *(const float4*)(Brow + 4);

    {
        float av[8] = {a0.x, a0.y, a0.z, a0.w, a1.x, a1.y, a1.z, a1.w};
        float bv[8] = {b0.x, b0.y, b0.z, b0.w, b1.x, b1.y, b1.z, b1.w};
#pragma unroll
        for (int t = 0; t < 8; t++) {
            As[0][8 * lg + t][lr] = av[t];
            Bd[0][8 * lg + t][2 * lr] = bv[t];
            Bd[0][8 * lg + t][2 * lr + 1] = bv[t];
        }
    }
    __syncthreads();

    const int nIter = K / 16;
    int s = 0;
    for (int it = 0; it < nIter; ++it) {
        if (it + 1 < nIter) {
            int k0n = (it + 1) * 16;
            a0 = *(const float4*)(Arow + k0n);
            a1 = *(const float4*)(Arow + k0n + 4);
            b0 = *(const float4*)(Brow + k0n);
            b1 = *(const float4*)(Brow + k0n + 4);
        }

#pragma unroll
        for (int kk = 0; kk < 16; kk++) {
            const float* ap = &As[s][kk][16 * ty];
            ulonglong2 A0 = *(const ulonglong2*)(ap);
            ulonglong2 A1 = *(const ulonglong2*)(ap + 4);
            ulonglong2 A2 = *(const ulonglong2*)(ap + 8);
            ulonglong2 A3 = *(const ulonglong2*)(ap + 12);
            const float* bp = &Bd[s][kk][8 * tx];
            ulonglong2 B0 = *(const ulonglong2*)(bp);
            ulonglong2 B1 = *(const ulonglong2*)(bp + 4);
            u64 ar[8] = {A0.x, A0.y, A1.x, A1.y, A2.x, A2.y, A3.x, A3.y};
            u64 br[4] = {B0.x, B0.y, B1.x, B1.y};
#pragma unroll
            for (int p = 0; p < 8; p++)
#pragma unroll
                for (int j = 0; j < 4; j++)
                    acc[p][j] = ffma2(ar[p], br[j], acc[p][j]);
        }

        if (it + 1 < nIter) {
            float av[8] = {a0.x, a0.y, a0.z, a0.w, a1.x, a1.y, a1.z, a1.w};
            float bv[8] = {b0.x, b0.y, b0.z, b0.w, b1.x, b1.y, b1.z, b1.w};
            int ns = 1 - s;
#pragma unroll
            for (int t = 0; t < 8; t++) {
                As[ns][8 * lg + t][lr] = av[t];
                Bd[ns][8 * lg + t][2 * lr] = bv[t];
                Bd[ns][8 * lg + t][2 * lr + 1] = bv[t];
            }
            __syncthreads();
            s = ns;
        }
    }

    float4 bi = *(const float4*)&bias[n0 + 4 * tx];
#pragma unroll
    for (int p = 0; p < 8; p++) {
        int r0 = m0 + 16 * ty + 2 * p;
        float2 c0 = unpack2(acc[p][0]);
        float2 c1 = unpack2(acc[p][1]);
        float2 c2 = unpack2(acc[p][2]);
        float2 c3 = unpack2(acc[p][3]);
        float4 e0 = make_float4(c0.x + bi.x, c1.x + bi.y, c2.x + bi.z, c3.x + bi.w);
        float4 e1 = make_float4(c0.y + bi.x, c1.y + bi.y, c2.y + bi.z, c3.y + bi.w);
        int cb0 = r0 / cRPB;
        float* Cr0 = C + (long long)cb0 * cBS + (long long)(r0 - cb0 * cRPB) * N;
        int r1 = r0 + 1;
        int cb1 = r1 / cRPB;
        float* Cr1 = C + (long long)cb1 * cBS + (long long)(r1 - cb1 * cRPB) * N;
        *(float4*)&Cr0[n0 + 4 * tx] = e0;
        *(float4*)&Cr1[n0 + 4 * tx] = e1;
    }
}

// ---------------------------------------------------------------------------
// Split QKV + RMSNorm + RoPE. One warp per (b, n, head).
// ---------------------------------------------------------------------------
__global__ void __launch_bounds__(256)
qkv_post(const float* __restrict__ qs1, const float* __restrict__ ks1,
         const float* __restrict__ qs2, const float* __restrict__ ks2)
{
    int w = (blockIdx.x * blockDim.x + threadIdx.x) >> 5;
    int lane = threadIdx.x & 31;
    int h = w & 15;
    int n = (w >> 4) & (NT - 1);
    int b = w >> 15;

    const float* row = g_qkv + (long long)(b * NT + n) * (3 * DM);
    const float* qs = (n < NSEG1) ? qs1 : qs2;
    const float* ks = (n < NSEG1) ? ks1 : ks2;

    float pos = (float)n;
    float e = (float)(2 * lane) * (1.0f / 64.0f);
    float invf = expf(-e * 9.210340371976184f);   // ln(10000)
    float ang = pos * invf;
    float cs = cosf(ang), sn = sinf(ang);

    long long obase = ((long long)(b * NH + h) * NT + n) * HD + 2 * lane;
    int doff = h * HD + 2 * lane;

    {
        float2 v = *(const float2*)(row + doff);
        float ss = v.x * v.x + v.y * v.y;
#pragma unroll
        for (int off = 16; off; off >>= 1) ss += __shfl_xor_sync(0xffffffffu, ss, off);
        float inv = rsqrtf(ss * (1.0f / 64.0f) + 1e-6f);
        float a = v.x * inv * qs[2 * lane];
        float c = v.y * inv * qs[2 * lane + 1];
        float2 o = make_float2(a * cs - c * sn, a * sn + c * cs);
        *(float2*)(g_q + obase) = o;
    }
    {
        float2 v = *(const float2*)(row + DM + doff);
        float ss = v.x * v.x + v.y * v.y;
#pragma unroll
        for (int off = 16; off; off >>= 1) ss += __shfl_xor_sync(0xffffffffu, ss, off);
        float inv = rsqrtf(ss * (1.0f / 64.0f) + 1e-6f);
        float a = v.x * inv * ks[2 * lane];
        float c = v.y * inv * ks[2 * lane + 1];
        float2 o = make_float2(a * cs - c * sn, a * sn + c * cs);
        *(float2*)(g_k + obase) = o;
    }
    {
        float2 v = *(const float2*)(row + 2 * DM + doff);
        *(float2*)(g_v + obase) = v;
    }
}

// ---------------------------------------------------------------------------
// Flash attention v3: 512 threads, Q-tile 256 x K-tile 64.
// Micro: 8 q-rows (4 packed pairs) x 4 k-cols (QK) / 4 d-cols (PV).
// K and V stored DUPLICATED in smem; P stored with XOR swizzle.
// All inner-loop FMAs are fma.rn.f32x2 with zero broadcast movs.
// ---------------------------------------------------------------------------
#define FA_QS   0                          // Qs[d][r]      : 64 x 256 floats
#define FA_KD   (64 * 256)                 // Kd[d][2c dup] : 64 x 128 floats
#define FA_VD   (64 * 256 + 64 * 128)      // Vd[k][2d dup] : 64 x 132 floats (padded)
#define FA_PS   (FA_VD + 64 * 132)         // Ps[k][r^swz]  : 64 x 256 floats
#define FA_FLOATS (FA_PS + 64 * 256)
#define FA_SMEM_BYTES (FA_FLOATS * 4)

__global__ void __launch_bounds__(512, 1)
flash_attn()
{
    extern __shared__ float sm[];
    float* Qs = sm + FA_QS;
    float* Kd = sm + FA_KD;
    float* Vd = sm + FA_VD;
    float* Ps = sm + FA_PS;

    const int b = blockIdx.z, h = blockIdx.y;
    const int q0 = blockIdx.x * 256;
    const int tid = threadIdx.x;
    const int tx = tid & 15;          // 4-col group
    const int ty = tid >> 4;          // 0..31, rows 8*ty..8*ty+7

    const long long bh = (long long)(b * NH + h) * NT;
    const float* Qbase = g_q + bh * HD;
    const float* Kbase = g_k + bh * HD;
    const float* Vbase = g_v + bh * HD;

    // ---- Q fill: transpose into Qs[d][r], pre-scaled by 1/8 ----
    {
        int lr = tid >> 1, lg = tid & 1;
        const float* qrow = Qbase + (long long)(q0 + lr) * HD + 32 * lg;
#pragma unroll
        for (int c = 0; c < 8; c++) {
            float4 v = *(const float4*)(qrow + 4 * c);
            int d = 32 * lg + 4 * c;
            Qs[(d + 0) * 256 + lr] = v.x * 0.125f;
            Qs[(d + 1) * 256 + lr] = v.y * 0.125f;
            Qs[(d + 2) * 256 + lr] = v.z * 0.125f;
            Qs[(d + 3) * 256 + lr] = v.w * 0.125f;
        }
    }

    // ---- K/V loader mapping ----
    const int klr = tid & 63;         // key row within tile
    const int klg = tid >> 6;         // d-octet 0..7
    const float* kptr = Kbase + (long long)klr * HD + 8 * klg;
    const float* vptr = Vbase + (long long)klr * HD + 8 * klg;

    u64 oacc[4][4];
    float mreg[8], lreg[8];
#pragma unroll
    for (int m = 0; m < 4; m++)
#pragma unroll
        for (int j = 0; j < 4; j++) oacc[m][j] = 0ull;
#pragma unroll
    for (int i = 0; i < 8; i++) { mreg[i] = -1e30f; lreg[i] = 0.0f; }

    // preload tile 0
    float4 kv0 = *(const float4*)(kptr);
    float4 kv1 = *(const float4*)(kptr + 4);
    float4 vv0 = *(const float4*)(vptr);
    float4 vv1 = *(const float4*)(vptr + 4);

    for (int kt = 0; kt < NT; kt += 64) {
        __syncthreads();   // prev PV done with Vd/Ps; (first iter: Qs fill visible too)
        {
            float kv[8] = {kv0.x, kv0.y, kv0.z, kv0.w, kv1.x, kv1.y, kv1.z, kv1.w};
            float vv[8] = {vv0.x, vv0.y, vv0.z, vv0.w, vv1.x, vv1.y, vv1.z, vv1.w};
#pragma unroll
            for (int t = 0; t < 8; t++) {
                int d = 8 * klg + t;
                Kd[d * 128 + 2 * klr] = kv[t];
                Kd[d * 128 + 2 * klr + 1] = kv[t];
                Vd[klr * 132 + 2 * d] = vv[t];
                Vd[klr * 132 + 2 * d + 1] = vv[t];
            }
        }
        __syncthreads();

        if (kt + 64 < NT) {
            kptr += 64 * HD; vptr += 64 * HD;
            kv0 = *(const float4*)(kptr);
            kv1 = *(const float4*)(kptr + 4);
            vv0 = *(const float4*)(vptr);
            vv1 = *(const float4*)(vptr + 4);
        }

        // ---- S = Q^T K ----
        u64 sacc[4][4];
#pragma unroll
        for (int m = 0; m < 4; m++)
#pragma unroll
            for (int j = 0; j < 4; j++) sacc[m][j] = 0ull;

#pragma unroll 8
        for (int d = 0; d < 64; d++) {
            const float* qp = &Qs[d * 256 + 8 * ty];
            ulonglong2 QA = *(const ulonglong2*)(qp);
            ulonglong2 QB = *(const ulonglong2*)(qp + 4);
            const float* kp = &Kd[d * 128 + 8 * tx];
            ulonglong2 KA = *(const ulonglong2*)(kp);
            ulonglong2 KB = *(const ulonglong2*)(kp + 4);
            u64 ar[4] = {QA.x, QA.y, QB.x, QB.y};
            u64 br[4] = {KA.x, KA.y, KB.x, KB.y};
#pragma unroll
            for (int m = 0; m < 4; m++)
#pragma unroll
                for (int j = 0; j < 4; j++)
                    sacc[m][j] = ffma2(ar[m], br[j], sacc[m][j]);
        }

        // ---- online softmax (rows replicated over 16-lane half-warps) ----
        float fi[8];
#pragma unroll
        for (int i = 0; i < 8; i++) {
            int m = i >> 1;
            float s[4];
            if ((i & 1) == 0) {
                s[0] = unpack2(sacc[m][0]).x; s[1] = unpack2(sacc[m][1]).x;
                s[2] = unpack2(sacc[m][2]).x; s[3] = unpack2(sacc[m][3]).x;
            } else {
                s[0] = unpack2(sacc[m][0]).y; s[1] = unpack2(sacc[m][1]).y;
                s[2] = unpack2(sacc[m][2]).y; s[3] = unpack2(sacc[m][3]).y;
            }
            float mt = fmaxf(fmaxf(s[0], s[1]), fmaxf(s[2], s[3]));
#pragma unroll
            for (int off = 8; off; off >>= 1) mt = fmaxf(mt, __shfl_xor_sync(0xffffffffu, mt, off));
            float nm = fmaxf(mreg[i], mt);
            float f = fexp(mreg[i] - nm);
            mreg[i] = nm;
            float p0 = fexp(s[0] - nm);
            float p1 = fexp(s[1] - nm);
            float p2 = fexp(s[2] - nm);
            float p3 = fexp(s[3] - nm);
            float ts = (p0 + p1) + (p2 + p3);
#pragma unroll
            for (int off = 8; off; off >>= 1) ts += __shfl_xor_sync(0xffffffffu, ts, off);
            lreg[i] = lreg[i] * f + ts;
            fi[i] = f;

            int r = 8 * ty + i;
            int k0 = 4 * tx;
            Ps[(k0 + 0) * 256 + (r ^ ((k0 + 0) & 0x1C))] = p0;
            Ps[(k0 + 1) * 256 + (r ^ ((k0 + 1) & 0x1C))] = p1;
            Ps[(k0 + 2) * 256 + (r ^ ((k0 + 2) & 0x1C))] = p2;
            Ps[(k0 + 3) * 256 + (r ^ ((k0 + 3) & 0x1C))] = p3;
        }

        // rescale O
#pragma unroll
        for (int m = 0; m < 4; m++) {
            u64 f2 = pack2(fi[2 * m], fi[2 * m + 1]);
#pragma unroll
            for (int j = 0; j < 4; j++)
                oacc[m][j] = fmul2(oacc[m][j], f2);
        }
        __syncthreads();   // P visible

        // ---- O += P V ----
#pragma unroll 4
        for (int k = 0; k < 64; k++) {
            int xw = k & 0x1C;
            const float* pp = &Ps[k * 256 + ((8 * ty) ^ xw)];
            ulonglong2 PA = *(const ulonglong2*)(pp);
            const float* pp2 = &Ps[k * 256 + ((8 * ty + 4) ^ xw)];
            ulonglong2 PB = *(const ulonglong2*)(pp2);
            const float* vp = &Vd[k * 132 + 8 * tx];
            ulonglong2 VA = *(const ulonglong2*)(vp);
            ulonglong2 VB = *(const ulonglong2*)(vp + 4);
            u64 pr[4] = {PA.x, PA.y, PB.x, PB.y};
            u64 vr[4] = {VA.x, VA.y, VB.x, VB.y};
#pragma unroll
            for (int m = 0; m < 4; m++)
#pragma unroll
                for (int j = 0; j < 4; j++)
                    oacc[m][j] = ffma2(pr[m], vr[j], oacc[m][j]);
        }
    }

    // ---- finalize: write x in (b, n, h*64 + d) layout ----
#pragma unroll
    for (int m = 0; m < 4; m++) {
        int r0 = q0 + 8 * ty + 2 * m;
        float inv0 = 1.0f / lreg[2 * m];
        float inv1 = 1.0f / lreg[2 * m + 1];
        float2 c0 = unpack2(oacc[m][0]);
        float2 c1 = unpack2(oacc[m][1]);
        float2 c2 = unpack2(oacc[m][2]);
        float2 c3 = unpack2(oacc[m][3]);
        float4 e0 = make_float4(c0.x * inv0, c1.x * inv0, c2.x * inv0, c3.x * inv0);
        float4 e1 = make_float4(c0.y * inv1, c1.y * inv1, c2.y * inv1, c3.y * inv1);
        *(float4*)&g_x[((long long)b * NT + r0) * DM + h * HD + 4 * tx] = e0;
        *(float4*)&g_x[((long long)b * NT + r0 + 1) * DM + h * HD + 4 * tx] = e1;
    }
}

// ---------------------------------------------------------------------------
// Launch
// ---------------------------------------------------------------------------
extern "C" void kernel_launch(void* const* d_in, const int* in_sizes, int n_in,
                              void* d_out, int out_size)
{
    const float* x1  = (const float*)d_in[0];
    const float* x2  = (const float*)d_in[1];
    const float* Wq1 = (const float*)d_in[2];
    const float* bq1 = (const float*)d_in[3];
    const float* Wq2 = (const float*)d_in[4];
    const float* bq2 = (const float*)d_in[5];
    const float* Wo1 = (const float*)d_in[6];
    const float* bo1 = (const float*)d_in[7];
    const float* Wo2 = (const float*)d_in[8];
    const float* bo2 = (const float*)d_in[9];
    const float* qs1 = (const float*)d_in[10];
    const float* ks1 = (const float*)d_in[11];
    const float* qs2 = (const float*)d_in[12];
    const float* ks2 = (const float*)d_in[13];
    float* out = (float*)d_out;

    float *qkv, *xbuf;
    cudaGetSymbolAddress((void**)&qkv, g_qkv);
    cudaGetSymbolAddress((void**)&xbuf, g_x);

    cudaFuncSetAttribute(flash_attn, cudaFuncAttributeMaxDynamicSharedMemorySize,
                         FA_SMEM_BYTES);

    // QKV projections into combined (b, 2048, 3072) scratch
    gemm_nt<<<dim3(3072 / 128, 3072 / 128), 256>>>(
        x1, Wq1, bq1, qkv,
        3072, 1024,
        NSEG1, (long long)NSEG1 * DM,
        NSEG1, (long long)NT * 3 * DM);
    gemm_nt<<<dim3(3072 / 128, 1024 / 128), 256>>>(
        x2, Wq2, bq2, qkv + (long long)NSEG1 * 3 * DM,
        3072, 1024,
        NSEG2, (long long)NSEG2 * DM,
        NSEG2, (long long)NT * 3 * DM);

    // Split + RMSNorm + RoPE -> g_q/g_k/g_v
    qkv_post<<<(BATCH * NT * NH) / 8, 256>>>(qs1, ks1, qs2, ks2);

    // Attention -> g_x
    flash_attn<<<dim3(NT / 256, NH, BATCH), 512, FA_SMEM_BYTES>>>();

    // Output projections (out1 then out2, concatenated in d_out)
    gemm_nt<<<dim3(1024 / 128, 3072 / 128), 256>>>(
        xbuf, Wo1, bo1, out,
        1024, 1024,
        NSEG1, (long long)NT * DM,
        NSEG1, (long long)NSEG1 * DM);
    gemm_nt<<<dim3(1024 / 128, 1024 / 128), 256>>>(
        xbuf + (long long)NSEG1 * DM, Wo2, bo2, out + (long long)BATCH * NSEG1 * DM,
        1024, 1024,
        NSEG2, (long long)NT * DM,
        NSEG2, (long long)NSEG2 * DM);
}

// round 5
// speedup vs baseline: 1.5287x; 1.5287x over previous
#include <cuda_runtime.h>
#include <cstdint>
#include <math.h>

#define BATCH 2
#define NT    2048
#define NSEG1 1536
#define NSEG2 512
#define DM    1024
#define NH    16
#define HD    64

typedef unsigned long long u64;
typedef unsigned int u32;

// Scratch (static device arrays — no allocation)
static __device__ float g_qkv[BATCH * NT * 3 * DM];   // (b, n, 3*1024)
static __device__ float g_q[BATCH * NH * NT * HD];    // (b, h, n, d)
static __device__ float g_k[BATCH * NH * NT * HD];
static __device__ float g_v[BATCH * NH * NT * HD];
static __device__ float g_x[BATCH * NT * DM];         // attention out, (b, n, h*d)

// ---------------------------------------------------------------------------
// Packed fp32 helpers (Blackwell fma.rn.f32x2 — ptxas never auto-fuses)
// ---------------------------------------------------------------------------
__device__ __forceinline__ u64 ffma2(u64 a, u64 b, u64 c) {
    u64 d;
    asm("fma.rn.f32x2 %0, %1, %2, %3;" : "=l"(d) : "l"(a), "l"(b), "l"(c));
    return d;
}
__device__ __forceinline__ u64 fmul2(u64 a, u64 b) {
    u64 d;
    asm("mul.rn.f32x2 %0, %1, %2;" : "=l"(d) : "l"(a), "l"(b));
    return d;
}
__device__ __forceinline__ u64 bcast2(float x) {
    u64 r;
    asm("mov.b64 %0, {%1, %1};" : "=l"(r) : "f"(x));
    return r;
}
__device__ __forceinline__ float2 unpack2(u64 v) {
    float2 f;
    asm("mov.b64 {%0, %1}, %2;" : "=f"(f.x), "=f"(f.y) : "l"(v));
    return f;
}

// cp.async helpers
__device__ __forceinline__ void cp16(u32 saddr, const void* gptr) {
    asm volatile("cp.async.ca.shared.global [%0], [%1], 16;" :: "r"(saddr), "l"(gptr));
}
__device__ __forceinline__ void cp_commit() {
    asm volatile("cp.async.commit_group;");
}
__device__ __forceinline__ void cp_wait1() {
    asm volatile("cp.async.wait_group 1;");
}
__device__ __forceinline__ void cp_wait0() {
    asm volatile("cp.async.wait_group 0;");
}

// ---------------------------------------------------------------------------
// Fast exp on the FMA pipe (avoids MUFU rt=8 bottleneck); valid x <= 0
// ---------------------------------------------------------------------------
__device__ __forceinline__ float fexp(float x) {
    x = fmaxf(x, -80.0f);
    float t = x * 1.4426950408889634f;
    float n = rintf(t);
    float f = t - n;
    float z = f * 0.6931471805599453f;
    float p = 1.0f + z * (1.0f + z * (0.5f + z * (0.16666667f + z * (0.041666667f + z * 0.008333334f))));
    int ni = (int)n;
    float s = __int_as_float((ni + 127) << 23);
    return p * s;
}

// ---------------------------------------------------------------------------
// NT GEMM: C[m, n] = sum_k A[m, k] * B[n, k] + bias[n]
// 128x128x16 tiles, 256 threads, 8x8 micro (split-4 rows/cols), packed
// FFMA2 along columns, scalar-bcast rows. Double-buffered smem, 1 sync/chunk.
// ---------------------------------------------------------------------------
__global__ void __launch_bounds__(256, 2)
gemm_nt(const float* __restrict__ A, const float* __restrict__ B,
        const float* __restrict__ bias, float* __restrict__ C,
        int N, int K,
        int aRPB, long long aBS,      // A rows-per-batch, batch stride (elems)
        int cRPB, long long cBS)      // C rows-per-batch, batch stride (elems)
{
    __shared__ float As[2][16][128];
    __shared__ float Bs[2][16][128];

    const int tid = threadIdx.x;
    const int tx = tid & 15;        // col groups {4tx, 64+4tx}
    const int ty = tid >> 4;        // row groups {4ty, 64+4ty}
    const int m0 = blockIdx.y * 128;
    const int n0 = blockIdx.x * 128;

    const int lr = tid >> 1;          // 0..127
    const int lg = (tid & 1) * 2;     // float4-group 0 or 2

    const int am = m0 + lr;
    const int ab = am / aRPB;
    const float* Arow = A + (long long)ab * aBS + (long long)(am - ab * aRPB) * K;
    const float* Brow = B + (long long)(n0 + lr) * K;

    u64 acc[8][4];
#pragma unroll
    for (int i = 0; i < 8; i++)
#pragma unroll
        for (int j = 0; j < 4; j++) acc[i][j] = 0ull;

    // preload chunk 0 into regs, store to buf 0
    float4 a0 = *(const float4*)(Arow + 4 * lg);
    float4 a1 = *(const float4*)(Arow + 4 * lg + 4);
    float4 b0 = *(const float4*)(Brow + 4 * lg);
    float4 b1 = *(const float4*)(Brow + 4 * lg + 4);
    {
        float av[8] = {a0.x, a0.y, a0.z, a0.w, a1.x, a1.y, a1.z, a1.w};
        float bv[8] = {b0.x, b0.y, b0.z, b0.w, b1.x, b1.y, b1.z, b1.w};
#pragma unroll
        for (int t = 0; t < 8; t++) {
            As[0][4 * lg + t][lr] = av[t];
            Bs[0][4 * lg + t][lr] = bv[t];
        }
    }
    __syncthreads();

    const int nIter = K / 16;
    int s = 0;
    for (int it = 0; it < nIter; ++it) {
        if (it + 1 < nIter) {
            int k0n = (it + 1) * 16;
            a0 = *(const float4*)(Arow + k0n + 4 * lg);
            a1 = *(const float4*)(Arow + k0n + 4 * lg + 4);
            b0 = *(const float4*)(Brow + k0n + 4 * lg);
            b1 = *(const float4*)(Brow + k0n + 4 * lg + 4);
        }

#pragma unroll
        for (int kk = 0; kk < 16; kk++) {
            float4 av0 = *(const float4*)&As[s][kk][4 * ty];
            float4 av1 = *(const float4*)&As[s][kk][64 + 4 * ty];
            ulonglong2 bv0 = *(const ulonglong2*)&Bs[s][kk][4 * tx];
            ulonglong2 bv1 = *(const ulonglong2*)&Bs[s][kk][64 + 4 * tx];
            float ar[8] = {av0.x, av0.y, av0.z, av0.w, av1.x, av1.y, av1.z, av1.w};
            u64 br[4] = {bv0.x, bv0.y, bv1.x, bv1.y};
#pragma unroll
            for (int i = 0; i < 8; i++) {
                u64 ai = bcast2(ar[i]);
#pragma unroll
                for (int j = 0; j < 4; j++)
                    acc[i][j] = ffma2(ai, br[j], acc[i][j]);
            }
        }

        if (it + 1 < nIter) {
            int ns = s ^ 1;
            float av[8] = {a0.x, a0.y, a0.z, a0.w, a1.x, a1.y, a1.z, a1.w};
            float bv[8] = {b0.x, b0.y, b0.z, b0.w, b1.x, b1.y, b1.z, b1.w};
#pragma unroll
            for (int t = 0; t < 8; t++) {
                As[ns][4 * lg + t][lr] = av[t];
                Bs[ns][4 * lg + t][lr] = bv[t];
            }
            __syncthreads();
            s = ns;
        }
    }

    float4 biA = *(const float4*)&bias[n0 + 4 * tx];
    float4 biB = *(const float4*)&bias[n0 + 64 + 4 * tx];
#pragma unroll
    for (int i = 0; i < 8; i++) {
        int row = m0 + ((i < 4) ? (4 * ty + i) : (64 + 4 * ty + i - 4));
        int cb = row / cRPB;
        float* Crow = C + (long long)cb * cBS + (long long)(row - cb * cRPB) * N;
        float2 p0 = unpack2(acc[i][0]);
        float2 p1 = unpack2(acc[i][1]);
        float2 p2 = unpack2(acc[i][2]);
        float2 p3 = unpack2(acc[i][3]);
        float4 oA = make_float4(p0.x + biA.x, p0.y + biA.y, p1.x + biA.z, p1.y + biA.w);
        float4 oB = make_float4(p2.x + biB.x, p2.y + biB.y, p3.x + biB.z, p3.y + biB.w);
        *(float4*)&Crow[n0 + 4 * tx] = oA;
        *(float4*)&Crow[n0 + 64 + 4 * tx] = oB;
    }
}

// ---------------------------------------------------------------------------
// Split QKV + RMSNorm + RoPE. One warp per (b, n, head).
// ---------------------------------------------------------------------------
__global__ void __launch_bounds__(256)
qkv_post(const float* __restrict__ qs1, const float* __restrict__ ks1,
         const float* __restrict__ qs2, const float* __restrict__ ks2)
{
    int w = (blockIdx.x * blockDim.x + threadIdx.x) >> 5;
    int lane = threadIdx.x & 31;
    int h = w & 15;
    int n = (w >> 4) & (NT - 1);
    int b = w >> 15;

    const float* row = g_qkv + (long long)(b * NT + n) * (3 * DM);
    const float* qs = (n < NSEG1) ? qs1 : qs2;
    const float* ks = (n < NSEG1) ? ks1 : ks2;

    float pos = (float)n;
    float e = (float)(2 * lane) * (1.0f / 64.0f);
    float invf = expf(-e * 9.210340371976184f);   // ln(10000)
    float ang = pos * invf;
    float cs = cosf(ang), sn = sinf(ang);

    long long obase = ((long long)(b * NH + h) * NT + n) * HD + 2 * lane;
    int doff = h * HD + 2 * lane;

    {
        float2 v = *(const float2*)(row + doff);
        float ss = v.x * v.x + v.y * v.y;
#pragma unroll
        for (int off = 16; off; off >>= 1) ss += __shfl_xor_sync(0xffffffffu, ss, off);
        float inv = rsqrtf(ss * (1.0f / 64.0f) + 1e-6f);
        float a = v.x * inv * qs[2 * lane];
        float c = v.y * inv * qs[2 * lane + 1];
        float2 o = make_float2(a * cs - c * sn, a * sn + c * cs);
        *(float2*)(g_q + obase) = o;
    }
    {
        float2 v = *(const float2*)(row + DM + doff);
        float ss = v.x * v.x + v.y * v.y;
#pragma unroll
        for (int off = 16; off; off >>= 1) ss += __shfl_xor_sync(0xffffffffu, ss, off);
        float inv = rsqrtf(ss * (1.0f / 64.0f) + 1e-6f);
        float a = v.x * inv * ks[2 * lane];
        float c = v.y * inv * ks[2 * lane + 1];
        float2 o = make_float2(a * cs - c * sn, a * sn + c * cs);
        *(float2*)(g_k + obase) = o;
    }
    {
        float2 v = *(const float2*)(row + 2 * DM + doff);
        *(float2*)(g_v + obase) = v;
    }
}

// ---------------------------------------------------------------------------
// Flash attention v4 (round-2 geometry + cp.async V + reduced registers):
// 128 q-rows x 128 k-cols per tile, 256 threads, 8x8 micro (QK), 8x4 (PV).
// K staged through 8 float4 regs (transpose store); V via cp.async into a
// double buffer (no transpose needed). P swizzled (r ^ (k & 0x1C)).
// smem: Qs 32K + Ks 32K + Vs 2x32K + Ps 64K = 192KB -> 1 CTA/SM.
// ---------------------------------------------------------------------------
#define FA_QS   0                        // Qs[d][r]  : 64 x 128
#define FA_KS   (64 * 128)               // Ks[d][c]  : 64 x 128
#define FA_VS   (2 * 64 * 128)           // Vs[2][k][d]: 2 x 128 x 64
#define FA_PS   (FA_VS + 2 * 128 * 64)   // Ps[k][r^] : 128 x 128
#define FA_FLOATS (FA_PS + 128 * 128)
#define FA_SMEM_BYTES (FA_FLOATS * 4)

__global__ void __launch_bounds__(256, 1)
flash_attn()
{
    extern __shared__ float sm[];
    float* Qs = sm + FA_QS;
    float* Ks = sm + FA_KS;
    float* Vs = sm + FA_VS;
    float* Ps = sm + FA_PS;

    const int b = blockIdx.z, h = blockIdx.y;
    const int q0 = blockIdx.x * 128;
    const int tid = threadIdx.x;
    const int tx = tid & 15, ty = tid >> 4;

    const long long bh = (long long)(b * NH + h) * NT;
    const float* Qbase = g_q + bh * HD;
    const float* Kbase = g_k + bh * HD;
    const float* Vbase = g_v + bh * HD;

    const int lr = tid >> 1;        // 0..127 (row)
    const int lg = tid & 1;         // half of d (32 floats)

    // ---- Q fill (transposed, pre-scaled by softmax scale 1/8) ----
    {
        const float* qrow = Qbase + (long long)(q0 + lr) * HD + lg * 32;
#pragma unroll
        for (int c = 0; c < 8; c++) {
            float4 v = *(const float4*)(qrow + 4 * c);
            int d = lg * 32 + 4 * c;
            Qs[(d + 0) * 128 + lr] = v.x * 0.125f;
            Qs[(d + 1) * 128 + lr] = v.y * 0.125f;
            Qs[(d + 2) * 128 + lr] = v.z * 0.125f;
            Qs[(d + 3) * 128 + lr] = v.w * 0.125f;
        }
    }

    // ---- V cp.async mapping: thread -> (row lr, 128B half lg) ----
    const float* vsrc = Vbase + (long long)lr * HD + 32 * lg;
    u32 vdst0 = (u32)__cvta_generic_to_shared(Vs + lr * 64 + 32 * lg);

    // prologue: V tile 0 async, K tile 0 regs
    {
#pragma unroll
        for (int j = 0; j < 8; j++) cp16(vdst0 + 16 * j, vsrc + 4 * j);
        cp_commit();
    }
    float4 kv[8];
    {
        const float* krow = Kbase + (long long)lr * HD + lg * 32;
#pragma unroll
        for (int c = 0; c < 8; c++) kv[c] = *(const float4*)(krow + 4 * c);
    }

    u64 oacc[8][2];
    float mreg[8], lreg[8];
#pragma unroll
    for (int i = 0; i < 8; i++) {
        mreg[i] = -1e30f; lreg[i] = 0.0f;
        oacc[i][0] = 0ull; oacc[i][1] = 0ull;
    }

    const int nTiles = NT / 128;
    for (int t = 0; t < nTiles; ++t) {
        const int s = t & 1;
        const float* Vcur = Vs + s * (128 * 64);

        __syncthreads();   // prev PV done (Ps, Vs[s^1]); prev QK done with Ks; Qs fill (t=0)

        // store K_t into Ks (transposed)
#pragma unroll
        for (int c = 0; c < 8; c++) {
            int d = lg * 32 + 4 * c;
            Ks[(d + 0) * 128 + lr] = kv[c].x;
            Ks[(d + 1) * 128 + lr] = kv[c].y;
            Ks[(d + 2) * 128 + lr] = kv[c].z;
            Ks[(d + 3) * 128 + lr] = kv[c].w;
        }

        if (t + 1 < nTiles) {
            // prefetch V_{t+1} into the other buffer
            const float* vn = vsrc + (long long)(t + 1) * 128 * HD;
            u32 vd = vdst0 + (u32)((s ^ 1) * (128 * 64 * 4));
#pragma unroll
            for (int j = 0; j < 8; j++) cp16(vd + 16 * j, vn + 4 * j);
            cp_commit();
            cp_wait1();   // V_t complete (V_{t+1} may remain in flight)
            // prefetch K_{t+1} into regs
            const float* krow = Kbase + (long long)(t + 1) * 128 * HD + (long long)lr * HD + lg * 32;
#pragma unroll
            for (int c = 0; c < 8; c++) kv[c] = *(const float4*)(krow + 4 * c);
        } else {
            cp_wait0();   // V_t complete
        }
        __syncthreads();   // Ks + Vs[s] visible

        // ---- S = Q^T K : 8x8 micro ----
        u64 sacc[8][4];
#pragma unroll
        for (int i = 0; i < 8; i++)
#pragma unroll
            for (int j = 0; j < 4; j++) sacc[i][j] = 0ull;

#pragma unroll 8
        for (int d = 0; d < 64; d++) {
            float4 av0 = *(const float4*)&Qs[d * 128 + 4 * ty];
            float4 av1 = *(const float4*)&Qs[d * 128 + 64 + 4 * ty];
            ulonglong2 bv0 = *(const ulonglong2*)&Ks[d * 128 + 4 * tx];
            ulonglong2 bv1 = *(const ulonglong2*)&Ks[d * 128 + 64 + 4 * tx];
            float ar[8] = {av0.x, av0.y, av0.z, av0.w, av1.x, av1.y, av1.z, av1.w};
            u64 br[4] = {bv0.x, bv0.y, bv1.x, bv1.y};
#pragma unroll
            for (int i = 0; i < 8; i++) {
                u64 ai = bcast2(ar[i]);
#pragma unroll
                for (int j = 0; j < 4; j++)
                    sacc[i][j] = ffma2(ai, br[j], sacc[i][j]);
            }
        }

        // ---- online softmax (rows replicated over 16-lane groups) ----
#pragma unroll
        for (int i = 0; i < 8; i++) {
            float sv[8];
            float2 tt;
            tt = unpack2(sacc[i][0]); sv[0] = tt.x; sv[1] = tt.y;
            tt = unpack2(sacc[i][1]); sv[2] = tt.x; sv[3] = tt.y;
            tt = unpack2(sacc[i][2]); sv[4] = tt.x; sv[5] = tt.y;
            tt = unpack2(sacc[i][3]); sv[6] = tt.x; sv[7] = tt.y;

            float mt = fmaxf(fmaxf(fmaxf(sv[0], sv[1]), fmaxf(sv[2], sv[3])),
                             fmaxf(fmaxf(sv[4], sv[5]), fmaxf(sv[6], sv[7])));
#pragma unroll
            for (int off = 8; off; off >>= 1) mt = fmaxf(mt, __shfl_xor_sync(0xffffffffu, mt, off));
            float nm = fmaxf(mreg[i], mt);
            float f = fexp(mreg[i] - nm);
            mreg[i] = nm;

            float p[8];
            float ts = 0.0f;
#pragma unroll
            for (int j = 0; j < 8; j++) {
                p[j] = fexp(sv[j] - nm);
                ts += p[j];
            }
#pragma unroll
            for (int off = 8; off; off >>= 1) ts += __shfl_xor_sync(0xffffffffu, ts, off);
            lreg[i] = lreg[i] * f + ts;

            u64 f2 = bcast2(f);
            oacc[i][0] = fmul2(oacc[i][0], f2);
            oacc[i][1] = fmul2(oacc[i][1], f2);

            int ri = (i < 4) ? (4 * ty + i) : (64 + 4 * ty + i - 4);
#pragma unroll
            for (int j = 0; j < 8; j++) {
                int kc = (j < 4) ? (4 * tx + j) : (64 + 4 * tx + j - 4);
                Ps[kc * 128 + (ri ^ (kc & 0x1C))] = p[j];
            }
        }
        __syncthreads();   // Ps visible

        // ---- O += P V : 8 rows x 4 d-cols ----
#pragma unroll 8
        for (int k = 0; k < 128; k++) {
            int xw = k & 0x1C;
            float4 a0 = *(const float4*)&Ps[k * 128 + ((4 * ty) ^ xw)];
            float4 a1 = *(const float4*)&Ps[k * 128 + 64 + ((4 * ty) ^ xw)];
            ulonglong2 bv = *(const ulonglong2*)&Vcur[k * 64 + 4 * tx];
            float ar[8] = {a0.x, a0.y, a0.z, a0.w, a1.x, a1.y, a1.z, a1.w};
#pragma unroll
            for (int i = 0; i < 8; i++) {
                u64 ai = bcast2(ar[i]);
                oacc[i][0] = ffma2(ai, bv.x, oacc[i][0]);
                oacc[i][1] = ffma2(ai, bv.y, oacc[i][1]);
            }
        }
    }

    // ---- finalize: write x in (b, n, h*64 + d) layout ----
#pragma unroll
    for (int i = 0; i < 8; i++) {
        float inv = 1.0f / lreg[i];
        int row = q0 + ((i < 4) ? (4 * ty + i) : (64 + 4 * ty + i - 4));
        float2 p0 = unpack2(oacc[i][0]);
        float2 p1 = unpack2(oacc[i][1]);
        float4 ov = make_float4(p0.x * inv, p0.y * inv, p1.x * inv, p1.y * inv);
        *(float4*)&g_x[((long long)b * NT + row) * DM + h * HD + 4 * tx] = ov;
    }
}

// ---------------------------------------------------------------------------
// Launch
// ---------------------------------------------------------------------------
extern "C" void kernel_launch(void* const* d_in, const int* in_sizes, int n_in,
                              void* d_out, int out_size)
{
    const float* x1  = (const float*)d_in[0];
    const float* x2  = (const float*)d_in[1];
    const float* Wq1 = (const float*)d_in[2];
    const float* bq1 = (const float*)d_in[3];
    const float* Wq2 = (const float*)d_in[4];
    const float* bq2 = (const float*)d_in[5];
    const float* Wo1 = (const float*)d_in[6];
    const float* bo1 = (const float*)d_in[7];
    const float* Wo2 = (const float*)d_in[8];
    const float* bo2 = (const float*)d_in[9];
    const float* qs1 = (const float*)d_in[10];
    const float* ks1 = (const float*)d_in[11];
    const float* qs2 = (const float*)d_in[12];
    const float* ks2 = (const float*)d_in[13];
    float* out = (float*)d_out;

    float *qkv, *xbuf;
    cudaGetSymbolAddress((void**)&qkv, g_qkv);
    cudaGetSymbolAddress((void**)&xbuf, g_x);

    cudaFuncSetAttribute(flash_attn, cudaFuncAttributeMaxDynamicSharedMemorySize,
                         FA_SMEM_BYTES);

    // QKV projections into combined (b, 2048, 3072) scratch
    gemm_nt<<<dim3(3072 / 128, 3072 / 128), 256>>>(
        x1, Wq1, bq1, qkv,
        3072, 1024,
        NSEG1, (long long)NSEG1 * DM,
        NSEG1, (long long)NT * 3 * DM);
    gemm_nt<<<dim3(3072 / 128, 1024 / 128), 256>>>(
        x2, Wq2, bq2, qkv + (long long)NSEG1 * 3 * DM,
        3072, 1024,
        NSEG2, (long long)NSEG2 * DM,
        NSEG2, (long long)NT * 3 * DM);

    // Split + RMSNorm + RoPE -> g_q/g_k/g_v
    qkv_post<<<(BATCH * NT * NH) / 8, 256>>>(qs1, ks1, qs2, ks2);

    // Attention -> g_x
    flash_attn<<<dim3(NT / 128, NH, BATCH), 256, FA_SMEM_BYTES>>>();

    // Output projections (out1 then out2, concatenated in d_out)
    gemm_nt<<<dim3(1024 / 128, 3072 / 128), 256>>>(
        xbuf, Wo1, bo1, out,
        1024, 1024,
        NSEG1, (long long)NT * DM,
        NSEG1, (long long)NSEG1 * DM);
    gemm_nt<<<dim3(1024 / 128, 1024 / 128), 256>>>(
        xbuf + (long long)NSEG1 * DM, Wo2, bo2, out + (long long)BATCH * NSEG1 * DM,
        1024, 1024,
        NSEG2, (long long)NT * DM,
        NSEG2, (long long)NSEG2 * DM);
}